// round 4
// baseline (speedup 1.0000x reference)
#include <cuda_runtime.h>
#include <math.h>

#define TT   128      // timesteps
#define BB   128      // batch
#define EMBD 300
#define UU   512
#define GG   2048     // 4*U
#define TBROWS (TT*BB)

// ---------------- scratch (static device arrays; no allocation) -------------
static __device__ float g_X[TBROWS*EMBD];                 // [t][b][e]
static __device__ float g_Zpre[2][TBROWS*GG];             // per dir: x@W + b for all (t,b)
static __device__ float g_Hseq[2][2][TBROWS*UU];          // [dir][ping][(s*B+r)*U + col]
static __device__ float g_C[2][BB*UU];                    // cell state per dir
static __device__ float g_mid[BB*(UU/2)];                 // dense0 output

// ---------------- embedding gather ------------------------------------------
__global__ void embed_kernel(const int* __restrict__ ids, const float* __restrict__ emb) {
    int idx = blockIdx.x*256 + threadIdx.x;
    if (idx >= TBROWS*EMBD) return;
    int row = idx / EMBD;           // t*BB + b
    int e   = idx - row*EMBD;
    int t   = row >> 7;             // / BB
    int b   = row & 127;
    g_X[idx] = emb[(size_t)ids[b*TT + t]*EMBD + e];
}

// ---------------- input projection: Zpre = In @ W + bias --------------------
// BM=64, BN=64, BK=16, 256 threads, 4x4 per thread. grid: (GG/64, TBROWS/64, 2)
__global__ void pregemm_kernel(const float* __restrict__ Wf, const float* __restrict__ bf,
                               const float* __restrict__ Wb, const float* __restrict__ bbv,
                               int layer)
{
    int d = blockIdx.z;
    const float* W    = d ? Wb  : Wf;
    const float* bias = d ? bbv : bf;
    const float* A    = (layer == 0) ? g_X : g_Hseq[d][(layer + 1) & 1];
    int K             = (layer == 0) ? EMBD : UU;
    float* Z = g_Zpre[d];

    int n0 = blockIdx.x * 64;
    int m0 = blockIdx.y * 64;
    int tid = threadIdx.x;
    int tx = tid & 15, ty = tid >> 4;

    __shared__ float As[16][64];
    __shared__ float Bs[16][64];
    float acc[4][4] = {};

    int nch = (K + 15) >> 4;
    for (int ch = 0; ch < nch; ++ch) {
        int k0 = ch << 4;
        // A tile: 64 rows x 16 k  (store k-major)
        int lr = tid >> 2;
        int lc = (tid & 3) << 2;
        #pragma unroll
        for (int q = 0; q < 4; ++q) {
            int k = k0 + lc + q;
            As[lc + q][lr] = (k < K) ? A[(size_t)(m0 + lr)*K + k] : 0.f;
        }
        // B tile: 16 k x 64 n
        int lc2 = tid & 63;
        int lr2 = tid >> 6;
        #pragma unroll
        for (int q = 0; q < 4; ++q) {
            int kk = lr2 + q*4;
            int k  = k0 + kk;
            Bs[kk][lc2] = (k < K) ? W[(size_t)k*GG + n0 + lc2] : 0.f;
        }
        __syncthreads();
        #pragma unroll
        for (int kk = 0; kk < 16; ++kk) {
            float4 a = *(const float4*)&As[kk][ty*4];
            float4 b = *(const float4*)&Bs[kk][tx*4];
            float av[4] = {a.x, a.y, a.z, a.w};
            float bv[4] = {b.x, b.y, b.z, b.w};
            #pragma unroll
            for (int i = 0; i < 4; ++i)
                #pragma unroll
                for (int j = 0; j < 4; ++j)
                    acc[i][j] += av[i]*bv[j];
        }
        __syncthreads();
    }
    #pragma unroll
    for (int i = 0; i < 4; ++i) {
        int m = m0 + ty*4 + i;
        #pragma unroll
        for (int j = 0; j < 4; ++j) {
            int n = n0 + tx*4 + j;
            Z[(size_t)m*GG + n] = acc[i][j] + bias[n];
        }
    }
}

// ---------------- one recurrent step (both directions) ----------------------
// block tile: 32 rows x 32 h-cols; each thread: 4 rows x (4 gate cols for one h-col)
// grid: (UU/32, BB/32, 2), 256 threads
__global__ void lstm_step_kernel(const float* __restrict__ Uf, const float* __restrict__ Ub,
                                 int layer, int s)
{
    int d = blockIdx.z;
    const float* Uw = d ? Ub : Uf;
    const float* Zp = g_Zpre[d];
    int ping  = layer & 1;
    float* Hcur = g_Hseq[d][ping];
    float* Cst  = g_C[d];

    int c0 = blockIdx.x << 5;
    int r0 = blockIdx.y << 5;
    int tid = threadIdx.x;
    int tx = tid & 31;
    int ty = tid >> 5;

    float acc[4][4] = {};   // [row i][gate g]

    if (s > 0) {
        const float* Hprev = Hcur + (size_t)(s - 1)*BB*UU;
        __shared__ float Hs[16][32];
        __shared__ float Us[16][128];
        for (int k0 = 0; k0 < UU; k0 += 16) {
            #pragma unroll
            for (int q = 0; q < 2; ++q) {
                int e = tid + q*256;
                int lr = e >> 4, lk = e & 15;
                Hs[lk][lr] = Hprev[(size_t)(r0 + lr)*UU + k0 + lk];
            }
            #pragma unroll
            for (int q = 0; q < 8; ++q) {
                int e = tid + q*256;
                int lk = e >> 7, lc = e & 127;
                int gg = lc >> 5, cc = lc & 31;
                Us[lk][lc] = Uw[(size_t)(k0 + lk)*GG + gg*UU + c0 + cc];
            }
            __syncthreads();
            #pragma unroll
            for (int kk = 0; kk < 16; ++kk) {
                float4 a = *(const float4*)&Hs[kk][ty*4];
                float b0 = Us[kk][tx],      b1 = Us[kk][32 + tx];
                float b2 = Us[kk][64 + tx], b3 = Us[kk][96 + tx];
                float av[4] = {a.x, a.y, a.z, a.w};
                float bv[4] = {b0, b1, b2, b3};
                #pragma unroll
                for (int i = 0; i < 4; ++i)
                    #pragma unroll
                    for (int g = 0; g < 4; ++g)
                        acc[i][g] += av[i]*bv[g];
            }
            __syncthreads();
        }
    }

    // epilogue: gates + state update (fully thread-local)
    int zr0 = (layer == 0 && d == 1) ? (TT - 1 - s) : s;   // bwd reads time-reversed layer-0 input
    int col = c0 + tx;
    #pragma unroll
    for (int i = 0; i < 4; ++i) {
        int r = r0 + ty*4 + i;
        size_t zoff = ((size_t)zr0*BB + r)*GG;
        float zi = acc[i][0] + Zp[zoff +          col];
        float zf = acc[i][1] + Zp[zoff +   UU  +  col];
        float zg = acc[i][2] + Zp[zoff + 2*UU  +  col];
        float zo = acc[i][3] + Zp[zoff + 3*UU  +  col];
        float ig = 1.f/(1.f + expf(-zi));
        float fg = 1.f/(1.f + expf(-zf));
        float sg = zg/(1.f + fabsf(zg));            // softsign
        float og = 1.f/(1.f + expf(-zo));
        float cprev = (s > 0) ? Cst[(size_t)r*UU + col] : 0.f;
        float cn = fg*cprev + ig*sg;
        float hn = og*(cn/(1.f + fabsf(cn)));
        Cst[(size_t)r*UU + col] = cn;
        Hcur[((size_t)s*BB + r)*UU + col] = hn;
    }
}

// ---------------- head: dense0 + BN + PReLU ---------------------------------
__global__ void dense0_kernel(const float* __restrict__ d0W, const float* __restrict__ d0b,
                              const float* __restrict__ gam, const float* __restrict__ bet,
                              const float* __restrict__ mea, const float* __restrict__ var,
                              const float* __restrict__ alp)
{
    int r = blockIdx.x;       // batch row
    int j = threadIdx.x;      // out col (256)
    __shared__ float addv[UU];
    const float* hf = &g_Hseq[0][0][((size_t)(TT - 1)*BB + r)*UU];   // layer 2 -> ping 0
    const float* hb = &g_Hseq[1][0][((size_t)(TT - 1)*BB + r)*UU];
    for (int k = j; k < UU; k += 256) addv[k] = 0.5f*(hf[k] + hb[k]);
    __syncthreads();
    float acc = d0b[j];
    for (int k = 0; k < UU; ++k) acc += addv[k]*d0W[k*(UU/2) + j];
    float y = (acc - mea[j])*rsqrtf(var[j] + 1e-3f)*gam[j] + bet[j];
    y = (y > 0.f) ? y : alp[j]*y;
    g_mid[r*(UU/2) + j] = y;
}

// ---------------- head: dense1 + softmax ------------------------------------
__global__ void dense1_kernel(const float* __restrict__ d1W, const float* __restrict__ d1b,
                              float* __restrict__ out)
{
    int r = threadIdx.x;
    if (r >= BB) return;
    float lg[7];
    #pragma unroll
    for (int j = 0; j < 7; ++j) lg[j] = d1b[j];
    const float* mid = &g_mid[r*(UU/2)];
    for (int k = 0; k < UU/2; ++k) {
        float v = mid[k];
        #pragma unroll
        for (int j = 0; j < 7; ++j) lg[j] += v*d1W[k*7 + j];
    }
    float m = lg[0];
    #pragma unroll
    for (int j = 1; j < 7; ++j) m = fmaxf(m, lg[j]);
    float s = 0.f, e[7];
    #pragma unroll
    for (int j = 0; j < 7; ++j) { e[j] = expf(lg[j] - m); s += e[j]; }
    float inv = 1.f/s;
    #pragma unroll
    for (int j = 0; j < 7; ++j) out[r*7 + j] = e[j]*inv;
}

// ---------------- launch ----------------------------------------------------
extern "C" void kernel_launch(void* const* d_in, const int* in_sizes, int n_in,
                              void* d_out, int out_size)
{
    (void)in_sizes; (void)n_in; (void)out_size;
    const int*   ids = (const int*)d_in[0];
    const float* emb = (const float*)d_in[1];
    const float* Wm[2][3]; const float* Um[2][3]; const float* bm[2][3];
    for (int d = 0; d < 2; ++d)
        for (int l = 0; l < 3; ++l) {
            int base = 2 + d*9 + l*3;
            Wm[d][l] = (const float*)d_in[base];
            Um[d][l] = (const float*)d_in[base + 1];
            bm[d][l] = (const float*)d_in[base + 2];
        }
    const float* d0W = (const float*)d_in[20];
    const float* d0b = (const float*)d_in[21];
    const float* gam = (const float*)d_in[22];
    const float* bet = (const float*)d_in[23];
    const float* mea = (const float*)d_in[24];
    const float* var = (const float*)d_in[25];
    const float* alp = (const float*)d_in[26];
    const float* d1W = (const float*)d_in[27];
    const float* d1b = (const float*)d_in[28];
    float* out = (float*)d_out;

    embed_kernel<<<(TBROWS*EMBD + 255)/256, 256>>>(ids, emb);

    for (int l = 0; l < 3; ++l) {
        dim3 gpre(GG/64, TBROWS/64, 2);
        pregemm_kernel<<<gpre, 256>>>(Wm[0][l], bm[0][l], Wm[1][l], bm[1][l], l);
        dim3 gstep(UU/32, BB/32, 2);
        for (int s = 0; s < TT; ++s)
            lstm_step_kernel<<<gstep, 256>>>(Um[0][l], Um[1][l], l, s);
    }

    dense0_kernel<<<BB, 256>>>(d0W, d0b, gam, bet, mea, var, alp);
    dense1_kernel<<<1, 128>>>(d1W, d1b, out);
}

// round 5
// speedup vs baseline: 1.7852x; 1.7852x over previous
#include <cuda_runtime.h>
#include <math.h>

#define TT   128      // timesteps
#define BB   128      // batch
#define EMBD 300
#define UU   512
#define GG   2048     // 4*U
#define TBROWS (TT*BB)
#define NBLK 128      // persistent blocks (<=148 SMs -> single wave, spin barrier safe)

// ---------------- scratch (static device arrays; no allocation) -------------
static __device__ float g_X[TBROWS*EMBD];                 // [t][b][e]
static __device__ float g_Zpre[2][TBROWS*GG];             // per dir: x@W + b for all (t,b)
static __device__ float g_Hseq[2][2][TBROWS*UU];          // [dir][ping][(s*B+r)*U + col]
static __device__ float g_HT[2][2][UU*BB];                // [dir][parity][col*BB + row]
static __device__ float g_mid[BB*(UU/2)];                 // dense0 output

// barrier state (zero-init; reset at end of each persistent kernel)
static __device__ unsigned g_bar_cnt = 0;
static __device__ unsigned g_bar_gen = 0;

__device__ __forceinline__ void grid_sync(unsigned target) {
    __syncthreads();
    if (threadIdx.x == 0) {
        __threadfence();
        unsigned old = atomicAdd(&g_bar_cnt, 1);
        if (old == NBLK - 1) {
            g_bar_cnt = 0;
            __threadfence();
            atomicAdd(&g_bar_gen, 1);
        } else {
            while (*(volatile unsigned*)&g_bar_gen < target) { }
        }
    }
    __syncthreads();
}

// ---------------- embedding gather ------------------------------------------
__global__ void embed_kernel(const int* __restrict__ ids, const float* __restrict__ emb) {
    int idx = blockIdx.x*256 + threadIdx.x;
    if (idx >= TBROWS*EMBD) return;
    int row = idx / EMBD;           // t*BB + b
    int e   = idx - row*EMBD;
    int t   = row >> 7;
    int b   = row & 127;
    g_X[idx] = emb[(size_t)ids[b*TT + t]*EMBD + e];
}

// ---------------- input projection: Zpre = In @ W + bias --------------------
// BM=128, BN=64, BK=16, 256 threads, 8x4 per thread. grid: (GG/64, TBROWS/128, 2)
__global__ void pregemm_kernel(const float* __restrict__ Wf, const float* __restrict__ bf,
                               const float* __restrict__ Wb, const float* __restrict__ bbv,
                               int layer)
{
    int d = blockIdx.z;
    const float* W    = d ? Wb  : Wf;
    const float* bias = d ? bbv : bf;
    const float* A    = (layer == 0) ? g_X : g_Hseq[d][(layer + 1) & 1];
    int K             = (layer == 0) ? EMBD : UU;
    float* Z = g_Zpre[d];

    int n0 = blockIdx.x * 64;
    int m0 = blockIdx.y * 128;
    int tid = threadIdx.x;
    int tx = tid & 15, ty = tid >> 4;

    __shared__ float As[16][132];   // padded: kills 4-way bank conflict on store
    __shared__ float Bs[16][64];
    float acc[8][4] = {};

    int nch = (K + 15) >> 4;
    for (int ch = 0; ch < nch; ++ch) {
        int k0 = ch << 4;
        // A tile: 128 rows x 16 k (K%4==0 for both 300 and 512 -> clean float4 guard)
        #pragma unroll
        for (int h = 0; h < 2; ++h) {
            int e = tid + h*256;
            int row = e >> 2, kq = (e & 3) << 2;
            float4 v = make_float4(0.f, 0.f, 0.f, 0.f);
            if (k0 + kq < K) v = *(const float4*)&A[(size_t)(m0 + row)*K + k0 + kq];
            As[kq + 0][row] = v.x; As[kq + 1][row] = v.y;
            As[kq + 2][row] = v.z; As[kq + 3][row] = v.w;
        }
        // B tile: 16 k x 64 n
        {
            int kk = tid >> 4, nq = (tid & 15) << 2;
            float4 v = make_float4(0.f, 0.f, 0.f, 0.f);
            if (k0 + kk < K) v = *(const float4*)&W[(size_t)(k0 + kk)*GG + n0 + nq];
            *(float4*)&Bs[kk][nq] = v;
        }
        __syncthreads();
        #pragma unroll
        for (int kk = 0; kk < 16; ++kk) {
            float4 a0 = *(const float4*)&As[kk][ty*8];
            float4 a1 = *(const float4*)&As[kk][ty*8 + 4];
            float4 b  = *(const float4*)&Bs[kk][tx*4];
            float av[8] = {a0.x, a0.y, a0.z, a0.w, a1.x, a1.y, a1.z, a1.w};
            float bv[4] = {b.x, b.y, b.z, b.w};
            #pragma unroll
            for (int i = 0; i < 8; ++i)
                #pragma unroll
                for (int j = 0; j < 4; ++j)
                    acc[i][j] += av[i]*bv[j];
        }
        __syncthreads();
    }
    #pragma unroll
    for (int i = 0; i < 8; ++i) {
        int m = m0 + ty*8 + i;
        int n = n0 + tx*4;
        float4 o;
        o.x = acc[i][0] + bias[n + 0];
        o.y = acc[i][1] + bias[n + 1];
        o.z = acc[i][2] + bias[n + 2];
        o.w = acc[i][3] + bias[n + 3];
        *(float4*)&Z[(size_t)m*GG + n] = o;
    }
}

// ---------------- persistent recurrent layer kernel -------------------------
// 128 blocks x 128 threads. Block: dir = bid>>6, 8 h-cols (c0 = (bid&63)*8).
// U slice resident in smem as float4{i,f,g,o} per (k, hcol). Cell state in regs.
// Per step: stream Hprev (transposed layout, coalesced ldcg) in 16-k chunks.
__global__ void lstm_layer_kernel(const float* __restrict__ Uf,
                                  const float* __restrict__ Ub, int layer)
{
    extern __shared__ char smem[];
    float4* Usv = (float4*)smem;              // [512][8] : k*8 + hc
    float*  Hs  = (float*)(smem + 65536);     // [16][128] : kk*128 + r

    int d   = blockIdx.x >> 6;
    int blk = blockIdx.x & 63;
    int c0  = blk << 3;
    const float* Uw = d ? Ub : Uf;
    const float* Zp = g_Zpre[d];
    int ping = layer & 1;
    float* Hseq = g_Hseq[d][ping];

    int tid = threadIdx.x;
    int tx = tid & 7;        // h-col within block
    int ty = tid >> 3;       // row-group (8 rows each)
    int j  = c0 + tx;        // global h index
    int r0 = ty << 3;

    // load U slice once (resident for all 128 steps)
    #pragma unroll 4
    for (int q = 0; q < 32; ++q) {
        int e  = q*128 + tid;
        int k  = e >> 3, hc = e & 7;
        int col = c0 + hc;
        float4 v;
        v.x = Uw[(size_t)k*GG +          col];
        v.y = Uw[(size_t)k*GG +   UU  +  col];
        v.z = Uw[(size_t)k*GG + 2*UU  +  col];
        v.w = Uw[(size_t)k*GG + 3*UU  +  col];
        Usv[k*8 + hc] = v;
    }
    __syncthreads();

    float c_reg[8];
    #pragma unroll
    for (int i = 0; i < 8; ++i) c_reg[i] = 0.f;

    unsigned bar = 0;
    for (int s = 0; s < TT; ++s) {
        // prefetch this step's Zpre rows (independent of H -> latency hides under matmul)
        int zr0 = (layer == 0 && d == 1) ? (TT - 1 - s) : s;
        float z0[8], z1[8], z2[8], z3[8];
        #pragma unroll
        for (int i = 0; i < 8; ++i) {
            const float* zp = Zp + ((size_t)zr0*BB + r0 + i)*GG + j;
            z0[i] = zp[0]; z1[i] = zp[UU]; z2[i] = zp[2*UU]; z3[i] = zp[3*UU];
        }

        float acc0[8] = {}, acc1[8] = {}, acc2[8] = {}, acc3[8] = {};
        if (s > 0) {
            const float4* HT = (const float4*)(g_HT[d][(s - 1) & 1]);
            float4 pf[4];
            #pragma unroll
            for (int q = 0; q < 4; ++q) pf[q] = __ldcg(HT + q*128 + tid);
            for (int ch = 0; ch < 32; ++ch) {
                #pragma unroll
                for (int q = 0; q < 4; ++q) ((float4*)Hs)[q*128 + tid] = pf[q];
                __syncthreads();
                if (ch < 31) {
                    const float4* src = HT + (ch + 1)*512;
                    #pragma unroll
                    for (int q = 0; q < 4; ++q) pf[q] = __ldcg(src + q*128 + tid);
                }
                #pragma unroll
                for (int kk = 0; kk < 16; ++kk) {
                    float4 u  = Usv[(ch*16 + kk)*8 + tx];
                    float4 a0 = *(const float4*)&Hs[kk*128 + r0];
                    float4 a1 = *(const float4*)&Hs[kk*128 + r0 + 4];
                    float av[8] = {a0.x, a0.y, a0.z, a0.w, a1.x, a1.y, a1.z, a1.w};
                    #pragma unroll
                    for (int i = 0; i < 8; ++i) {
                        acc0[i] += av[i]*u.x;
                        acc1[i] += av[i]*u.y;
                        acc2[i] += av[i]*u.z;
                        acc3[i] += av[i]*u.w;
                    }
                }
                __syncthreads();
            }
        }

        // gates + state update (thread-local)
        float hn[8];
        #pragma unroll
        for (int i = 0; i < 8; ++i) {
            float zi = acc0[i] + z0[i];
            float zf = acc1[i] + z1[i];
            float zg = acc2[i] + z2[i];
            float zo = acc3[i] + z3[i];
            float ig = 1.f/(1.f + expf(-zi));
            float fg = 1.f/(1.f + expf(-zf));
            float sg = zg/(1.f + fabsf(zg));
            float og = 1.f/(1.f + expf(-zo));
            float cn = fg*c_reg[i] + ig*sg;
            c_reg[i] = cn;
            hn[i] = og*(cn/(1.f + fabsf(cn)));
            Hseq[((size_t)s*BB + r0 + i)*UU + j] = hn[i];
        }
        float* HTc = g_HT[d][s & 1];
        *(float4*)&HTc[j*BB + r0]     = make_float4(hn[0], hn[1], hn[2], hn[3]);
        *(float4*)&HTc[j*BB + r0 + 4] = make_float4(hn[4], hn[5], hn[6], hn[7]);

        grid_sync(++bar);
    }

    // reset barrier generation for the next persistent launch / graph replay
    if (blockIdx.x == 0 && tid == 0) g_bar_gen = 0;
}

// ---------------- head: dense0 + BN + PReLU ---------------------------------
__global__ void dense0_kernel(const float* __restrict__ d0W, const float* __restrict__ d0b,
                              const float* __restrict__ gam, const float* __restrict__ bet,
                              const float* __restrict__ mea, const float* __restrict__ var,
                              const float* __restrict__ alp)
{
    int r = blockIdx.x;
    int jj = threadIdx.x;
    __shared__ float addv[UU];
    const float* hf = &g_Hseq[0][0][((size_t)(TT - 1)*BB + r)*UU];   // layer 2 -> ping 0
    const float* hb = &g_Hseq[1][0][((size_t)(TT - 1)*BB + r)*UU];
    for (int k = jj; k < UU; k += 256) addv[k] = 0.5f*(hf[k] + hb[k]);
    __syncthreads();
    float acc = d0b[jj];
    for (int k = 0; k < UU; ++k) acc += addv[k]*d0W[k*(UU/2) + jj];
    float y = (acc - mea[jj])*rsqrtf(var[jj] + 1e-3f)*gam[jj] + bet[jj];
    y = (y > 0.f) ? y : alp[jj]*y;
    g_mid[r*(UU/2) + jj] = y;
}

// ---------------- head: dense1 + softmax ------------------------------------
__global__ void dense1_kernel(const float* __restrict__ d1W, const float* __restrict__ d1b,
                              float* __restrict__ out)
{
    int r = threadIdx.x;
    if (r >= BB) return;
    float lg[7];
    #pragma unroll
    for (int j = 0; j < 7; ++j) lg[j] = d1b[j];
    const float* mid = &g_mid[r*(UU/2)];
    for (int k = 0; k < UU/2; ++k) {
        float v = mid[k];
        #pragma unroll
        for (int j = 0; j < 7; ++j) lg[j] += v*d1W[k*7 + j];
    }
    float m = lg[0];
    #pragma unroll
    for (int j = 1; j < 7; ++j) m = fmaxf(m, lg[j]);
    float ssum = 0.f, e[7];
    #pragma unroll
    for (int j = 0; j < 7; ++j) { e[j] = expf(lg[j] - m); ssum += e[j]; }
    float inv = 1.f/ssum;
    #pragma unroll
    for (int j = 0; j < 7; ++j) out[r*7 + j] = e[j]*inv;
}

// ---------------- launch ----------------------------------------------------
extern "C" void kernel_launch(void* const* d_in, const int* in_sizes, int n_in,
                              void* d_out, int out_size)
{
    (void)in_sizes; (void)n_in; (void)out_size;
    const int*   ids = (const int*)d_in[0];
    const float* emb = (const float*)d_in[1];
    const float* Wm[2][3]; const float* Um[2][3]; const float* bm[2][3];
    for (int d = 0; d < 2; ++d)
        for (int l = 0; l < 3; ++l) {
            int base = 2 + d*9 + l*3;
            Wm[d][l] = (const float*)d_in[base];
            Um[d][l] = (const float*)d_in[base + 1];
            bm[d][l] = (const float*)d_in[base + 2];
        }
    const float* d0W = (const float*)d_in[20];
    const float* d0b = (const float*)d_in[21];
    const float* gam = (const float*)d_in[22];
    const float* bet = (const float*)d_in[23];
    const float* mea = (const float*)d_in[24];
    const float* var = (const float*)d_in[25];
    const float* alp = (const float*)d_in[26];
    const float* d1W = (const float*)d_in[27];
    const float* d1b = (const float*)d_in[28];
    float* out = (float*)d_out;

    // opt-in smem for the persistent kernel (64KB U slice + 8KB H chunk)
    cudaFuncSetAttribute(lstm_layer_kernel,
                         cudaFuncAttributeMaxDynamicSharedMemorySize, 73728);

    embed_kernel<<<(TBROWS*EMBD + 255)/256, 256>>>(ids, emb);

    for (int l = 0; l < 3; ++l) {
        dim3 gpre(GG/64, TBROWS/128, 2);
        pregemm_kernel<<<gpre, 256>>>(Wm[0][l], bm[0][l], Wm[1][l], bm[1][l], l);
        lstm_layer_kernel<<<NBLK, 128, 73728>>>(Um[0][l], Um[1][l], l);
    }

    dense0_kernel<<<BB, 256>>>(d0W, d0b, gam, bet, mea, var, alp);
    dense1_kernel<<<1, 128>>>(d1W, d1b, out);
}